// round 1
// baseline (speedup 1.0000x reference)
#include <cuda_runtime.h>
#include <cuda_bf16.h>

// ---------------------------------------------------------------------------
// Fused ConditionedRecurrentEdgeModel
//   per edge:  w = relu(LN(winding @ Ww^T + bw))
//              x = [src,dest,edge_attr,u[batch],w]           (384)
//              x1 = relu(LN(x @ W1^T + b1))                  (128)
//              GRU(x1, h) -> h_new                           (128)
//              x_out = h_new @ Wx^T + bx                     (64)
// Strategy: 1 CTA = 64 edges, fp32 with packed fma.rn.f32x2, all stages fused,
// u-contribution to GEMM1 precomputed (batch has only 64 distinct values).
// ---------------------------------------------------------------------------

#define N_INC 64
#define E_INC 64
#define H2    128
#define H1    128
#define E_OUT 64
#define LN_EPS 1e-5f

#define BM 64            // edges per CTA
#define NT 256           // threads per CTA
#define XS_STR 324       // x tile stride (320 used cols + pad)
#define LSTR   132       // stride for 128-wide smem tiles
#define BSK    32        // K chunk

// smem layout (in floats)
#define X_S_OFF   0
#define X1_OFF    (BM * XS_STR)              // 20736
#define H_OFF     (X1_OFF + BM * LSTR)       // 29184
#define BS_OFF    (H_OFF + BM * LSTR)        // 37632  (2 * 32 * 132 = 8448)
#define WIN_OFF   (BS_OFF + 2 * BSK * LSTR)  // 46080  (128 floats)
#define BT_OFF    (WIN_OFF + 128)            // 46208  (64 ints)
#define SMEM_FLOATS (BT_OFF + 64)            // 46272
#define SMEM_BYTES  (SMEM_FLOATS * 4)        // 185088

__device__ float U1g[64 * 128];   // u @ W1_u^T  (per-batch precomputed)

// ---------------- packed f32x2 helpers ----------------
__device__ __forceinline__ void ffma2(unsigned long long &acc,
                                      unsigned long long a,
                                      unsigned long long b) {
    asm("fma.rn.f32x2 %0, %1, %2, %0;" : "+l"(acc) : "l"(a), "l"(b));
}
__device__ __forceinline__ unsigned long long bc2(float x) {
    unsigned long long r;
    asm("mov.b64 %0, {%1, %1};" : "=l"(r) : "f"(x));
    return r;
}
__device__ __forceinline__ float2 upk(unsigned long long v) {
    float2 f;
    asm("mov.b64 {%0, %1}, %2;" : "=f"(f.x), "=f"(f.y) : "l"(v));
    return f;
}
__device__ __forceinline__ float red16(float v) {
    v += __shfl_xor_sync(0xffffffffu, v, 8);
    v += __shfl_xor_sync(0xffffffffu, v, 4);
    v += __shfl_xor_sync(0xffffffffu, v, 2);
    v += __shfl_xor_sync(0xffffffffu, v, 1);
    return v;
}
__device__ __forceinline__ float sigf(float x) { return 1.f / (1.f + expf(-x)); }

// ---------------- weight staging: buf[kk][n] = Bg[n*ldg + kcol + kk] -------
template<int N>
__device__ __forceinline__ void stageB(float* buf, const float* __restrict__ Bg,
                                       int ldg, int kcol, int tid) {
    #pragma unroll
    for (int p = 0; p < N / 8; p++) {
        int idx = p * NT + tid;
        int kk = idx & 31;
        int n  = idx >> 5;
        buf[kk * LSTR + n] = Bg[n * ldg + kcol + kk];
    }
}

// ---------------- double-buffered GEMM over K (multiple of 32) -------------
// acc[i][p]: rows mg*4+i, col pair n0+2p. A is smem (stride LDA), B is gmem.
template<int LDA, int NPAIR>
__device__ __forceinline__ void gemm_loop(unsigned long long (&acc)[4][NPAIR],
                                          const float* As0,
                                          const float* __restrict__ Bg, int ldg,
                                          int K, float* Bs, int tid, int n0) {
    constexpr int NCOLS = NPAIR * 32;     // 128 or 64
    const int NC = K >> 5;
    stageB<NCOLS>(Bs, Bg, ldg, 0, tid);
    __syncthreads();
    for (int c = 0; c < NC; ++c) {
        if (c + 1 < NC)
            stageB<NCOLS>(Bs + ((c + 1) & 1) * (BSK * LSTR), Bg, ldg, (c + 1) * 32, tid);
        const float* B = Bs + (c & 1) * (BSK * LSTR) + n0;
        const float* A = As0 + c * 32;
        #pragma unroll 8
        for (int kk = 0; kk < 32; ++kk) {
            unsigned long long bp[NPAIR];
            #pragma unroll
            for (int p = 0; p < NPAIR / 2; p++) {
                ulonglong2 t = *reinterpret_cast<const ulonglong2*>(B + kk * LSTR + p * 4);
                bp[2 * p] = t.x;
                bp[2 * p + 1] = t.y;
            }
            #pragma unroll
            for (int i = 0; i < 4; i++) {
                unsigned long long a2 = bc2(A[i * LDA + kk]);
                #pragma unroll
                for (int p = 0; p < NPAIR; p++) ffma2(acc[i][p], a2, bp[p]);
            }
        }
        __syncthreads();
    }
}

// ---------------- U1 precompute: U1[b][n] = sum_k u[b][k] * W1[n][192+k] ----
__global__ void u1_kernel(const float* __restrict__ u, const float* __restrict__ W1) {
    int b = blockIdx.x;
    int n = threadIdx.x;
    float s = 0.f;
    #pragma unroll 8
    for (int k = 0; k < 64; k++)
        s += u[b * 64 + k] * W1[n * 384 + 192 + k];
    U1g[b * 128 + n] = s;
}

// ---------------- main fused kernel ----------------------------------------
__global__ __launch_bounds__(NT, 1)
void fused_kernel(const float* __restrict__ src, const float* __restrict__ dst,
                  const float* __restrict__ ea,  const float* __restrict__ hin,
                  const int*   __restrict__ batch, const float* __restrict__ winding,
                  const float* __restrict__ Ww,  const float* __restrict__ bw,
                  const float* __restrict__ gw,  const float* __restrict__ betaw,
                  const float* __restrict__ W1,  const float* __restrict__ b1,
                  const float* __restrict__ g1,  const float* __restrict__ beta1,
                  const float* __restrict__ Wih, const float* __restrict__ Whh,
                  const float* __restrict__ bih, const float* __restrict__ bhh,
                  const float* __restrict__ Wx,  const float* __restrict__ bx,
                  float* __restrict__ out_x, float* __restrict__ out_h, int E) {
    extern __shared__ float smem[];
    float* x_s  = smem + X_S_OFF;
    float* x1_s = smem + X1_OFF;     // also reused as hn_s
    float* h_s  = smem + H_OFF;
    float* Bs   = smem + BS_OFF;
    float* win_s = smem + WIN_OFF;
    int*   bt_s  = (int*)(smem + BT_OFF);
    float* r_s  = x_s;               // reuse of x tile after GEMM1
    float* z_s  = x_s + BM * LSTR;
    float* hn_s = x1_s;

    const int tid = threadIdx.x;
    const int mg  = tid >> 4;        // 0..15  (4 rows each)
    const int tn  = tid & 15;        // 0..15
    const int n0  = tn * 8;
    const int m0  = blockIdx.x * BM;

    // ---------------- Phase A: stage inputs ----------------
    if (tid < 64) {
        int r = tid;
        bt_s[r] = (m0 + r < E) ? batch[m0 + r] : 0;
    }
    if (tid < 128) {
        int r = tid >> 1, c = tid & 1;
        win_s[tid] = (m0 + r < E) ? winding[(m0 + r) * 2 + c] : 0.f;
    }
    {
        const float4 z4 = make_float4(0.f, 0.f, 0.f, 0.f);
        #pragma unroll
        for (int t = 0; t < 3; t++) {
            const float* g = (t == 0) ? src : (t == 1) ? dst : ea;
            int base = t * 64;
            #pragma unroll
            for (int p = 0; p < 4; p++) {
                int idx = p * NT + tid;
                int r = idx >> 4, c4 = idx & 15;
                float4 v = (m0 + r < E)
                    ? *reinterpret_cast<const float4*>(g + (size_t)(m0 + r) * 64 + c4 * 4) : z4;
                *reinterpret_cast<float4*>(x_s + r * XS_STR + base + c4 * 4) = v;
            }
        }
        #pragma unroll
        for (int p = 0; p < 8; p++) {
            int idx = p * NT + tid;
            int r = idx >> 5, c4 = idx & 31;
            float4 v = (m0 + r < E)
                ? *reinterpret_cast<const float4*>(hin + (size_t)(m0 + r) * 128 + c4 * 4) : z4;
            *reinterpret_cast<float4*>(h_s + r * LSTR + c4 * 4) = v;
        }
    }
    __syncthreads();

    // ---------------- Phase B: winding MLP -> x_s cols [192,320) ----------
    {
        float ww0[8], ww1[8], bwv[8], gwv[8], bev[8];
        #pragma unroll
        for (int j = 0; j < 8; j++) {
            int n = n0 + j;
            ww0[j] = Ww[n * 2 + 0];
            ww1[j] = Ww[n * 2 + 1];
            bwv[j] = bw[n]; gwv[j] = gw[n]; bev[j] = betaw[n];
        }
        #pragma unroll
        for (int i = 0; i < 4; i++) {
            int m = mg * 4 + i;
            float wa = win_s[2 * m], wb = win_s[2 * m + 1];
            float v[8], s = 0.f, q = 0.f;
            #pragma unroll
            for (int j = 0; j < 8; j++) {
                v[j] = fmaf(wa, ww0[j], fmaf(wb, ww1[j], bwv[j]));
                s += v[j]; q += v[j] * v[j];
            }
            s = red16(s); q = red16(q);
            float mu = s * (1.f / 128.f);
            float var = q * (1.f / 128.f) - mu * mu;
            float inv = rsqrtf(var + LN_EPS);
            #pragma unroll
            for (int j = 0; j < 8; j++) {
                float o = fmaf((v[j] - mu) * inv, gwv[j], bev[j]);
                x_s[m * XS_STR + 192 + n0 + j] = fmaxf(o, 0.f);
            }
        }
    }
    __syncthreads();

    // ---------------- GEMM1: x(320) @ W1^T  (+U1[batch]) -> LN -> relu -----
    {
        unsigned long long acc[4][4] = {};
        const float* Arow = x_s + mg * 4 * XS_STR;
        gemm_loop<XS_STR, 4>(acc, Arow,        W1,       384, 192, Bs, tid, n0);
        gemm_loop<XS_STR, 4>(acc, Arow + 192,  W1 + 256, 384, 128, Bs, tid, n0);

        float b1v[8], g1v[8], be1[8];
        #pragma unroll
        for (int j = 0; j < 8; j++) {
            int n = n0 + j;
            b1v[j] = b1[n]; g1v[j] = g1[n]; be1[j] = beta1[n];
        }
        #pragma unroll
        for (int i = 0; i < 4; i++) {
            int m = mg * 4 + i;
            const float* u1r = U1g + bt_s[m] * 128 + n0;
            float v[8], s = 0.f, q = 0.f;
            #pragma unroll
            for (int p = 0; p < 4; p++) {
                float2 f = upk(acc[i][p]);
                v[2 * p]     = f.x + b1v[2 * p]     + u1r[2 * p];
                v[2 * p + 1] = f.y + b1v[2 * p + 1] + u1r[2 * p + 1];
            }
            #pragma unroll
            for (int j = 0; j < 8; j++) { s += v[j]; q += v[j] * v[j]; }
            s = red16(s); q = red16(q);
            float mu = s * (1.f / 128.f);
            float var = q * (1.f / 128.f) - mu * mu;
            float inv = rsqrtf(var + LN_EPS);
            #pragma unroll
            for (int j = 0; j < 8; j++) {
                float o = fmaf((v[j] - mu) * inv, g1v[j], be1[j]);
                x1_s[m * LSTR + n0 + j] = fmaxf(o, 0.f);
            }
        }
    }
    __syncthreads();

    // ---------------- GRU: gates r, z, n -----------------------------------
    const float* x1row = x1_s + mg * 4 * LSTR;
    const float* hrow  = h_s  + mg * 4 * LSTR;
    for (int g = 0; g < 3; g++) {
        unsigned long long ai[4][4] = {};
        unsigned long long ah[4][4] = {};
        gemm_loop<LSTR, 4>(ai, x1row, Wih + g * 128 * 128, 128, 128, Bs, tid, n0);
        gemm_loop<LSTR, 4>(ah, hrow,  Whh + g * 128 * 128, 128, 128, Bs, tid, n0);

        float biv[8], bhv[8];
        #pragma unroll
        for (int j = 0; j < 8; j++) {
            biv[j] = bih[g * 128 + n0 + j];
            bhv[j] = bhh[g * 128 + n0 + j];
        }
        #pragma unroll
        for (int i = 0; i < 4; i++) {
            int m = mg * 4 + i;
            #pragma unroll
            for (int p = 0; p < 4; p++) {
                float2 fi = upk(ai[i][p]);
                float2 fh = upk(ah[i][p]);
                #pragma unroll
                for (int e = 0; e < 2; e++) {
                    int j = 2 * p + e;
                    float vi = (e ? fi.y : fi.x) + biv[j];
                    float vh = (e ? fh.y : fh.x) + bhv[j];
                    int a = m * LSTR + n0 + j;
                    if (g == 0) {
                        r_s[a] = sigf(vi + vh);
                    } else if (g == 1) {
                        z_s[a] = sigf(vi + vh);
                    } else {
                        float r  = r_s[a];
                        float zz = z_s[a];
                        float nn = tanhf(fmaf(r, vh, vi));
                        float hp = h_s[a];
                        hn_s[a] = fmaf(zz, hp - nn, nn);   // (1-z)*n + z*h
                    }
                }
            }
        }
    }
    __syncthreads();

    // ---------------- h_new -> gmem (coalesced) -----------------------------
    #pragma unroll
    for (int p = 0; p < 8; p++) {
        int idx = p * NT + tid;
        int r = idx >> 5, c4 = idx & 31;
        if (m0 + r < E) {
            float4 v = *reinterpret_cast<const float4*>(hn_s + r * LSTR + c4 * 4);
            *reinterpret_cast<float4*>(out_h + (size_t)(m0 + r) * 128 + c4 * 4) = v;
        }
    }

    // ---------------- x_out = h_new @ Wx^T + bx -----------------------------
    {
        unsigned long long aw[4][2] = {};
        const int n0w = tn * 4;
        gemm_loop<LSTR, 2>(aw, hn_s + mg * 4 * LSTR, Wx, 128, 128, Bs, tid, n0w);
        float bxv[4];
        #pragma unroll
        for (int j = 0; j < 4; j++) bxv[j] = bx[n0w + j];
        #pragma unroll
        for (int i = 0; i < 4; i++) {
            int m = mg * 4 + i;
            if (m0 + m < E) {
                float2 a = upk(aw[i][0]);
                float2 b = upk(aw[i][1]);
                float4 o = make_float4(a.x + bxv[0], a.y + bxv[1],
                                       b.x + bxv[2], b.y + bxv[3]);
                *reinterpret_cast<float4*>(out_x + (size_t)(m0 + m) * 64 + n0w) = o;
            }
        }
    }
}

// ---------------------------------------------------------------------------
extern "C" void kernel_launch(void* const* d_in, const int* in_sizes, int n_in,
                              void* d_out, int out_size) {
    const float* src     = (const float*)d_in[0];
    const float* dst     = (const float*)d_in[1];
    const float* ea      = (const float*)d_in[2];
    const float* hin     = (const float*)d_in[3];
    const float* u       = (const float*)d_in[4];
    const int*   batch   = (const int*)  d_in[5];
    const float* winding = (const float*)d_in[6];
    const float* Ww      = (const float*)d_in[7];
    const float* bw      = (const float*)d_in[8];
    const float* gw      = (const float*)d_in[9];
    const float* betaw   = (const float*)d_in[10];
    const float* W1      = (const float*)d_in[11];
    const float* b1      = (const float*)d_in[12];
    const float* g1      = (const float*)d_in[13];
    const float* beta1   = (const float*)d_in[14];
    const float* Wih     = (const float*)d_in[15];
    const float* Whh     = (const float*)d_in[16];
    const float* bih     = (const float*)d_in[17];
    const float* bhh     = (const float*)d_in[18];
    const float* Wx      = (const float*)d_in[19];
    const float* bx      = (const float*)d_in[20];

    int E = in_sizes[0] / 64;
    int B = in_sizes[4] / 64;

    float* out_x = (float*)d_out;                       // [E, 64]
    float* out_h = (float*)d_out + (size_t)E * 64;      // [E, 128]

    cudaFuncSetAttribute(fused_kernel,
                         cudaFuncAttributeMaxDynamicSharedMemorySize, SMEM_BYTES);

    u1_kernel<<<B, 128>>>(u, W1);
    int grid = (E + BM - 1) / BM;
    fused_kernel<<<grid, NT, SMEM_BYTES>>>(src, dst, ea, hin, batch, winding,
                                           Ww, bw, gw, betaw,
                                           W1, b1, g1, beta1,
                                           Wih, Whh, bih, bhh, Wx, bx,
                                           out_x, out_h, E);
}